// round 8
// baseline (speedup 1.0000x reference)
#include <cuda_runtime.h>
#include <cuda_bf16.h>
#include <math.h>
#include <stdint.h>
#include <mma.h>

using namespace nvcuda;

// Problem constants
#define BSZ   2
#define SEQ   2048
#define NH    16
#define HD    128
#define HID   2048
#define MROWS (BSZ*SEQ)           // 4096
#define MN    ((size_t)MROWS*HID) // 8388608
#define NZ    (BSZ*NH)            // 32 (b,h) pairs

#define BK    32
#define LDSA  40                  // smem leading dim for dense [row][k] tiles

// fused attention tiles
#define QB    64
#define KB    128
#define LDF   136

// ---------------- scratch (device globals; no allocation allowed) -------------
__device__ float g_qkv[3*MROWS*HID];            // raw Q,K,V projections [3][B*S, H*D]
__device__ float g_q[MROWS*HID];                // [B,H,S,D] after RoPE
__device__ float g_k[MROWS*HID];
__device__ float g_v[MROWS*HID];
__device__ float g_attn_t[MROWS*HID];           // attention out in [B*S, H*D]

// ---------------- cp.async helpers --------------------------------------------
__device__ __forceinline__ void cp16(void* smem_dst, const void* gsrc) {
    uint32_t s = (uint32_t)__cvta_generic_to_shared(smem_dst);
    asm volatile("cp.async.cg.shared.global [%0], [%1], 16;" :: "r"(s), "l"(gsrc));
}
#define CP_COMMIT() asm volatile("cp.async.commit_group;")
#define CP_WAIT0()  asm volatile("cp.async.wait_group 0;")

template <class Frag>
__device__ __forceinline__ void frag_to_tf32(Frag& f) {
    #pragma unroll
    for (int e = 0; e < f.num_elements; e++)
        f.x[e] = wmma::__float_to_tf32(f.x[e]);
}

// =====================================================================
// Dense WMMA tf32 NT GEMM (C = A * B^T), cp.async 2-stage pipeline.
// Block tile 128x128, BK=32, 256 threads (8 warps 2x4), warp 64x32.
// =====================================================================
__device__ __forceinline__ void dense_nt_body(
    const float* __restrict__ A, const float* __restrict__ B, float* __restrict__ C,
    int lda, int ldb, int ldc, int m0, int n0, int kTiles, float* dynsm)
{
    float* smA = dynsm;                       // [2][128*LDSA]
    float* smB = dynsm + 2 * 128 * LDSA;      // [2][128*LDSA]

    const int tid = threadIdx.x;
    const int wid = tid >> 5;
    const int warp_m = (wid >> 2) * 64;
    const int warp_n = (wid & 3) * 32;

    wmma::fragment<wmma::accumulator, 16, 16, 8, float> acc[4][2];
    #pragma unroll
    for (int mi = 0; mi < 4; mi++)
        #pragma unroll
        for (int ni = 0; ni < 2; ni++)
            wmma::fill_fragment(acc[mi][ni], 0.0f);

    auto issue = [&](int kt, int stg) {
        const int k0 = kt * BK;
        float* dA = smA + stg * 128 * LDSA;
        float* dB = smB + stg * 128 * LDSA;
        #pragma unroll
        for (int r = 0; r < 4; r++) {
            int idx = tid + r * 256;       // 0..1023
            int row = idx >> 3;            // 0..127
            int c4  = (idx & 7) << 2;      // 0..28
            cp16(dA + row * LDSA + c4, A + (size_t)(m0 + row) * lda + k0 + c4);
            cp16(dB + row * LDSA + c4, B + (size_t)(n0 + row) * ldb + k0 + c4);
        }
        CP_COMMIT();
    };

    issue(0, 0);
    for (int kt = 0; kt < kTiles; kt++) {
        CP_WAIT0();
        __syncthreads();
        if (kt + 1 < kTiles) issue(kt + 1, (kt + 1) & 1);
        const int stg = kt & 1;
        const float* cA = smA + stg * 128 * LDSA;
        const float* cB = smB + stg * 128 * LDSA;

        #pragma unroll
        for (int ks = 0; ks < BK; ks += 8) {
            wmma::fragment<wmma::matrix_a, 16, 16, 8, wmma::precision::tf32,
                           wmma::row_major> af[4];
            #pragma unroll
            for (int mi = 0; mi < 4; mi++) {
                wmma::load_matrix_sync(af[mi], cA + (warp_m + mi * 16) * LDSA + ks, LDSA);
                frag_to_tf32(af[mi]);
            }
            wmma::fragment<wmma::matrix_b, 16, 16, 8, wmma::precision::tf32,
                           wmma::col_major> bf[2];
            #pragma unroll
            for (int ni = 0; ni < 2; ni++) {
                wmma::load_matrix_sync(bf[ni], cB + (warp_n + ni * 16) * LDSA + ks, LDSA);
                frag_to_tf32(bf[ni]);
            }
            #pragma unroll
            for (int mi = 0; mi < 4; mi++)
                #pragma unroll
                for (int ni = 0; ni < 2; ni++)
                    wmma::mma_sync(acc[mi][ni], af[mi], bf[ni], acc[mi][ni]);
        }
        __syncthreads();
    }

    #pragma unroll
    for (int mi = 0; mi < 4; mi++)
        #pragma unroll
        for (int ni = 0; ni < 2; ni++) {
            size_t row = (size_t)(m0 + warp_m + mi * 16);
            int col = n0 + warp_n + ni * 16;
            wmma::store_matrix_sync(C + row * ldc + col, acc[mi][ni], ldc,
                                    wmma::mem_row_major);
        }
}

#define DENSE_SMEM (4 * 128 * LDSA * (int)sizeof(float))   // 81920 B

__global__ __launch_bounds__(256) void qkv_gemm_kernel(
    const float* __restrict__ X,
    const float* __restrict__ Wq,
    const float* __restrict__ Wk,
    const float* __restrict__ Wv)
{
    extern __shared__ float dynsm[];
    const float* W = (blockIdx.z == 0) ? Wq : (blockIdx.z == 1) ? Wk : Wv;
    float* C = g_qkv + (size_t)blockIdx.z * MN;
    dense_nt_body(X, W, C, HID, HID, HID,
                  blockIdx.y * 128, blockIdx.x * 128, HID / BK, dynsm);
}

__global__ __launch_bounds__(256) void out_gemm_kernel(
    const float* __restrict__ Wo, float* __restrict__ out)
{
    extern __shared__ float dynsm[];
    dense_nt_body(g_attn_t, Wo, out, HID, HID, HID,
                  blockIdx.y * 128, blockIdx.x * 128, HID / BK, dynsm);
}

// =====================================================================
// Fused flash attention: per (z, 64-row q-block), loop kv-blocks of 128.
// S=QK^T (wmma) -> smem -> fp32 online softmax -> P(tf32) -> O += P V (wmma).
// =====================================================================
__global__ __launch_bounds__(256, 1) void attn_kernel()
{
    extern __shared__ float sm[];
    float* smQ  = sm;                    // QB x LDF
    float* smKV = smQ  + QB * LDF;       // KB x LDF
    float* smS  = smKV + KB * LDF;       // QB x LDF
    float* smO  = smS  + QB * LDF;       // QB x 128 (fp32 accum)
    float* smM  = smO  + QB * 128;       // QB row max
    float* smL  = smM  + QB;             // QB row sum
    float* smC  = smL  + QB;             // QB corr

    const int z  = blockIdx.z;
    const int b  = z / NH, h = z % NH;
    const int q0 = blockIdx.y * QB;
    const int tid  = threadIdx.x;
    const int wid  = tid >> 5;
    const int lane = tid & 31;
    const int warp_m = (wid >> 2) * 32;   // 0 or 32
    const int warp_n = (wid & 3) * 32;    // 0,32,64,96

    const float* Qg = g_q + (size_t)z * SEQ * HD + (size_t)q0 * HD;
    const float* Kg = g_k + (size_t)z * SEQ * HD;
    const float* Vg = g_v + (size_t)z * SEQ * HD;
    const float scale = 0.08838834764831845f;  // 1/sqrt(128)

    // load Q block (QB x HD) raw fp32
    #pragma unroll
    for (int r = 0; r < 8; r++) {
        int idx = tid + r * 256;           // 0..2047
        int row = idx >> 5;
        int c4  = (idx & 31) << 2;
        *(float4*)(smQ + row * LDF + c4) = *(const float4*)(Qg + (size_t)row * HD + c4);
    }
    for (int i = tid; i < QB * 128; i += 256) smO[i] = 0.0f;
    if (tid < QB) { smM[tid] = -INFINITY; smL[tid] = 0.0f; smC[tid] = 0.0f; }

    const int nkb = (q0 + QB + KB - 1) / KB;
    for (int kb = 0; kb < nkb; kb++) {
        __syncthreads();
        // ---- load K block (KB x HD) ----
        #pragma unroll
        for (int r = 0; r < 16; r++) {
            int idx = tid + r * 256;       // 0..4095
            int row = idx >> 5;
            int c4  = (idx & 31) << 2;
            *(float4*)(smKV + row * LDF + c4) =
                *(const float4*)(Kg + (size_t)(kb * KB + row) * HD + c4);
        }
        __syncthreads();

        // ---- S = Q K^T : M=QB, N=KB, K=HD ----
        {
            wmma::fragment<wmma::accumulator, 16, 16, 8, float> sacc[2][2];
            #pragma unroll
            for (int mi = 0; mi < 2; mi++)
                #pragma unroll
                for (int ni = 0; ni < 2; ni++)
                    wmma::fill_fragment(sacc[mi][ni], 0.0f);

            #pragma unroll
            for (int ks = 0; ks < HD; ks += 8) {
                wmma::fragment<wmma::matrix_a, 16, 16, 8, wmma::precision::tf32,
                               wmma::row_major> af[2];
                #pragma unroll
                for (int mi = 0; mi < 2; mi++) {
                    wmma::load_matrix_sync(af[mi], smQ + (warp_m + mi * 16) * LDF + ks, LDF);
                    frag_to_tf32(af[mi]);
                }
                wmma::fragment<wmma::matrix_b, 16, 16, 8, wmma::precision::tf32,
                               wmma::col_major> bf[2];
                #pragma unroll
                for (int ni = 0; ni < 2; ni++) {
                    wmma::load_matrix_sync(bf[ni], smKV + (warp_n + ni * 16) * LDF + ks, LDF);
                    frag_to_tf32(bf[ni]);
                }
                #pragma unroll
                for (int mi = 0; mi < 2; mi++)
                    #pragma unroll
                    for (int ni = 0; ni < 2; ni++)
                        wmma::mma_sync(sacc[mi][ni], af[mi], bf[ni], sacc[mi][ni]);
            }
            #pragma unroll
            for (int mi = 0; mi < 2; mi++)
                #pragma unroll
                for (int ni = 0; ni < 2; ni++)
                    wmma::store_matrix_sync(smS + (warp_m + mi * 16) * LDF + warp_n + ni * 16,
                                            sacc[mi][ni], LDF, wmma::mem_row_major);
        }
        __syncthreads();

        // ---- online softmax: warp wid owns rows wid*8 .. wid*8+7 ----
        for (int rr = 0; rr < 8; rr++) {
            int r  = wid * 8 + rr;
            int qg = q0 + r;
            float x[4];
            float rm = -INFINITY;
            #pragma unroll
            for (int i = 0; i < 4; i++) {
                int c  = lane + i * 32;
                int kg = kb * KB + c;
                float v = smS[r * LDF + c] * scale;
                x[i] = (kg <= qg) ? v : -INFINITY;
                rm = fmaxf(rm, x[i]);
            }
            #pragma unroll
            for (int o = 16; o; o >>= 1) rm = fmaxf(rm, __shfl_xor_sync(0xffffffffu, rm, o));

            float mold = smM[r];
            float mnew = fmaxf(mold, rm);
            float corr = __expf(mold - mnew);

            float rs = 0.0f;
            #pragma unroll
            for (int i = 0; i < 4; i++) {
                float p = (x[i] == -INFINITY) ? 0.0f : __expf(x[i] - mnew);
                smS[r * LDF + lane + i * 32] = wmma::__float_to_tf32(p);
                rs += p;
            }
            #pragma unroll
            for (int o = 16; o; o >>= 1) rs += __shfl_xor_sync(0xffffffffu, rs, o);

            if (lane == 0) {
                smL[r] = smL[r] * corr + rs;
                smM[r] = mnew;
                smC[r] = corr;
            }
            // rescale O row by corr
            #pragma unroll
            for (int i = 0; i < 4; i++)
                smO[r * 128 + lane + i * 32] *= corr;
        }
        __syncthreads();

        // ---- load V block (KB x HD), overwrite smKV ----
        #pragma unroll
        for (int r = 0; r < 16; r++) {
            int idx = tid + r * 256;
            int row = idx >> 5;
            int c4  = (idx & 31) << 2;
            *(float4*)(smKV + row * LDF + c4) =
                *(const float4*)(Vg + (size_t)(kb * KB + row) * HD + c4);
        }
        __syncthreads();

        // ---- O_delta = P V : M=QB, N=HD, K=KB ----
        {
            wmma::fragment<wmma::accumulator, 16, 16, 8, float> oacc[2][2];
            #pragma unroll
            for (int mi = 0; mi < 2; mi++)
                #pragma unroll
                for (int ni = 0; ni < 2; ni++)
                    wmma::fill_fragment(oacc[mi][ni], 0.0f);

            #pragma unroll
            for (int ks = 0; ks < KB; ks += 8) {
                wmma::fragment<wmma::matrix_a, 16, 16, 8, wmma::precision::tf32,
                               wmma::row_major> af[2];
                #pragma unroll
                for (int mi = 0; mi < 2; mi++) {
                    wmma::load_matrix_sync(af[mi], smS + (warp_m + mi * 16) * LDF + ks, LDF);
                    frag_to_tf32(af[mi]);
                }
                wmma::fragment<wmma::matrix_b, 16, 16, 8, wmma::precision::tf32,
                               wmma::row_major> bf[2];
                #pragma unroll
                for (int ni = 0; ni < 2; ni++) {
                    wmma::load_matrix_sync(bf[ni], smKV + ks * LDF + warp_n + ni * 16, LDF);
                    frag_to_tf32(bf[ni]);
                }
                #pragma unroll
                for (int mi = 0; mi < 2; mi++)
                    #pragma unroll
                    for (int ni = 0; ni < 2; ni++)
                        wmma::mma_sync(oacc[mi][ni], af[mi], bf[ni], oacc[mi][ni]);
            }
            __syncthreads();   // all P reads done before overwriting smS
            #pragma unroll
            for (int mi = 0; mi < 2; mi++)
                #pragma unroll
                for (int ni = 0; ni < 2; ni++)
                    wmma::store_matrix_sync(smS + (warp_m + mi * 16) * LDF + warp_n + ni * 16,
                                            oacc[mi][ni], LDF, wmma::mem_row_major);
        }
        __syncthreads();

        // ---- O += O_delta ----
        for (int i = tid; i < QB * 128; i += 256) {
            int r = i >> 7, c = i & 127;
            smO[i] += smS[r * LDF + c];
        }
    }
    __syncthreads();

    // ---- write normalized output ----
    for (int i = tid; i < QB * 128; i += 256) {
        int r = i >> 7, c = i & 127;
        float o = smO[i] / smL[r];
        g_attn_t[((size_t)(b * SEQ) + q0 + r) * HID + (size_t)h * HD + c] = o;
    }
}

#define ATTN_SMEM ((QB*LDF + KB*LDF + QB*LDF + QB*128 + 3*QB) * (int)sizeof(float))

// ---------------- RoPE + transpose to [B,H,S,D] (Round-3 verified) -------------
__global__ __launch_bounds__(256) void rope_transpose_kernel()
{
    long long idx = (long long)blockIdx.x * blockDim.x + threadIdx.x;
    const long long total = (long long)BSZ * NH * SEQ * 64;
    if (idx >= total) return;

    int d = (int)(idx % 64);  long long r = idx / 64;
    int s = (int)(r % SEQ);   r /= SEQ;
    int h = (int)(r % NH);
    int b = (int)(r / NH);

    double inv_freq = exp(-((double)(2 * d) / (double)HD) * log(10000.0));
    double ang = (double)s * inv_freq;
    double cd, sd;
    sincos(ang, &sd, &cd);
    float c  = (float)cd;
    float sn = (float)sd;

    size_t src = ((size_t)b * SEQ + s) * HID + (size_t)h * HD + d;   // [B*S, H*D]
    size_t dst = (((size_t)b * NH + h) * SEQ + s) * HD + d;          // [B,H,S,D]

    const float* Q0 = g_qkv;
    const float* K0 = g_qkv + MN;
    const float* V0 = g_qkv + 2 * MN;

    float q0 = Q0[src], q1 = Q0[src + 64];
    g_q[dst]      = q0 * c - q1 * sn;
    g_q[dst + 64] = q1 * c + q0 * sn;

    float k0 = K0[src], k1 = K0[src + 64];
    g_k[dst]      = k0 * c - k1 * sn;
    g_k[dst + 64] = k1 * c + k0 * sn;

    g_v[dst]      = V0[src];
    g_v[dst + 64] = V0[src + 64];
}

// ---------------- launch -------------------------------------------------------
extern "C" void kernel_launch(void* const* d_in, const int* in_sizes, int n_in,
                              void* d_out, int out_size)
{
    const float* X  = (const float*)d_in[0];
    const float* Wq = (const float*)d_in[1];
    const float* Wk = (const float*)d_in[2];
    const float* Wv = (const float*)d_in[3];
    const float* Wo = (const float*)d_in[4];
    float* out = (float*)d_out;

    cudaFuncSetAttribute(qkv_gemm_kernel,
                         cudaFuncAttributeMaxDynamicSharedMemorySize, DENSE_SMEM);
    cudaFuncSetAttribute(out_gemm_kernel,
                         cudaFuncAttributeMaxDynamicSharedMemorySize, DENSE_SMEM);
    cudaFuncSetAttribute(attn_kernel,
                         cudaFuncAttributeMaxDynamicSharedMemorySize, ATTN_SMEM);

    // 1. QKV projections
    {
        dim3 grid(HID / 128, MROWS / 128, 3);
        qkv_gemm_kernel<<<grid, 256, DENSE_SMEM>>>(X, Wq, Wk, Wv);
    }
    // 2. RoPE + transpose
    {
        long long total = (long long)BSZ * NH * SEQ * 64;  // 4,194,304
        rope_transpose_kernel<<<(unsigned)((total + 255) / 256), 256>>>();
    }
    // 3. Fused attention (scores + softmax + PV)
    {
        dim3 grid(1, SEQ / QB, NZ);
        attn_kernel<<<grid, 256, ATTN_SMEM>>>();
    }
    // 4. Output projection
    {
        dim3 grid(HID / 128, MROWS / 128);
        out_gemm_kernel<<<grid, 256, DENSE_SMEM>>>(Wo, out);
    }
}

// round 9
// speedup vs baseline: 1.1465x; 1.1465x over previous
#include <cuda_runtime.h>
#include <cuda_bf16.h>
#include <math.h>
#include <stdint.h>
#include <mma.h>

using namespace nvcuda;

// Problem constants
#define BSZ   2
#define SEQ   2048
#define NH    16
#define HD    128
#define HID   2048
#define MROWS (BSZ*SEQ)           // 4096
#define MN    ((size_t)MROWS*HID) // 8388608
#define NZ    (BSZ*NH)            // 32 (b,h) pairs

#define BK    16
#define LDSA  20                  // smem leading dim for [row][k] tiles (BK=16 + pad)
#define LDSB  132                 // smem leading dim for [k][n] tiles (NN)

// ---------------- scratch (device globals; no allocation allowed) -------------
__device__ float g_qkv[3*MROWS*HID];            // raw Q,K,V projections [3][B*S, H*D]
__device__ float g_q[MROWS*HID];                // [B,H,S,D] after RoPE
__device__ float g_k[MROWS*HID];
__device__ float g_v[MROWS*HID];
__device__ float g_attn_t[MROWS*HID];           // attention out in [B*S, H*D]
__device__ float g_scores[(size_t)NZ*SEQ*SEQ];  // [B*H, S, S] scores/probs

// ---------------- cp.async helpers --------------------------------------------
__device__ __forceinline__ void cp16(void* smem_dst, const void* gsrc) {
    uint32_t s = (uint32_t)__cvta_generic_to_shared(smem_dst);
    asm volatile("cp.async.cg.shared.global [%0], [%1], 16;" :: "r"(s), "l"(gsrc));
}
#define CP_COMMIT() asm volatile("cp.async.commit_group;")
#define CP_WAIT0()  asm volatile("cp.async.wait_group 0;")

template <class Frag>
__device__ __forceinline__ void frag_to_tf32(Frag& f) {
    #pragma unroll
    for (int e = 0; e < f.num_elements; e++)
        f.x[e] = wmma::__float_to_tf32(f.x[e]);
}

// =====================================================================
// WMMA tf32 GEMM, cp.async 2-stage pipeline, tuned for 2 CTAs/SM.
// Block tile 128x128, BK=16, 256 threads (8 warps 2x4), warp 64x32.
//  - TRANSB=true : B is [N,K] row-major (C = A * B^T)
//  - TRANSB=false: B is [K,N] row-major (C = A * B)
// =====================================================================
template <bool TRANSB>
__device__ __forceinline__ void gemm_body(
    const float* __restrict__ A, const float* __restrict__ B, float* __restrict__ C,
    int lda, int ldb, int ldc, int m0, int n0, int kTiles, float* dynsm)
{
    float* smA = dynsm;                       // [2][128*LDSA]
    float* smB = dynsm + 2 * 128 * LDSA;      // [2][128*LDSA] or [2][16*LDSB]

    const int tid = threadIdx.x;
    const int wid = tid >> 5;
    const int warp_m = (wid >> 2) * 64;
    const int warp_n = (wid & 3) * 32;

    wmma::fragment<wmma::accumulator, 16, 16, 8, float> acc[4][2];
    #pragma unroll
    for (int mi = 0; mi < 4; mi++)
        #pragma unroll
        for (int ni = 0; ni < 2; ni++)
            wmma::fill_fragment(acc[mi][ni], 0.0f);

    auto issue = [&](int kt, int stg) {
        const int k0 = kt * BK;
        float* dA = smA + stg * 128 * LDSA;
        #pragma unroll
        for (int r = 0; r < 2; r++) {
            int idx = tid + r * 256;       // 0..511 float4s (128 rows x 4)
            int row = idx >> 2;            // 0..127
            int c4  = (idx & 3) << 2;      // 0,4,8,12
            cp16(dA + row * LDSA + c4, A + (size_t)(m0 + row) * lda + k0 + c4);
        }
        if (TRANSB) {
            float* dB = smB + stg * 128 * LDSA;
            #pragma unroll
            for (int r = 0; r < 2; r++) {
                int idx = tid + r * 256;
                int row = idx >> 2;
                int c4  = (idx & 3) << 2;
                cp16(dB + row * LDSA + c4, B + (size_t)(n0 + row) * ldb + k0 + c4);
            }
        } else {
            float* dB = smB + stg * 16 * LDSB;
            #pragma unroll
            for (int r = 0; r < 2; r++) {
                int idx = tid + r * 256;       // 0..511 (16 krows x 32)
                int krow = idx >> 5;           // 0..15
                int c4   = (idx & 31) << 2;    // 0..124
                cp16(dB + krow * LDSB + c4, B + (size_t)(k0 + krow) * ldb + n0 + c4);
            }
        }
        CP_COMMIT();
    };

    issue(0, 0);
    for (int kt = 0; kt < kTiles; kt++) {
        CP_WAIT0();
        __syncthreads();
        if (kt + 1 < kTiles) issue(kt + 1, (kt + 1) & 1);
        const int stg = kt & 1;
        const float* cA = smA + stg * 128 * LDSA;
        const float* cB = TRANSB ? (smB + stg * 128 * LDSA) : (smB + stg * 16 * LDSB);

        #pragma unroll
        for (int ks = 0; ks < BK; ks += 8) {
            wmma::fragment<wmma::matrix_a, 16, 16, 8, wmma::precision::tf32,
                           wmma::row_major> af[4];
            #pragma unroll
            for (int mi = 0; mi < 4; mi++) {
                wmma::load_matrix_sync(af[mi], cA + (warp_m + mi * 16) * LDSA + ks, LDSA);
                frag_to_tf32(af[mi]);
            }
            if (TRANSB) {
                wmma::fragment<wmma::matrix_b, 16, 16, 8, wmma::precision::tf32,
                               wmma::col_major> bf[2];
                #pragma unroll
                for (int ni = 0; ni < 2; ni++) {
                    wmma::load_matrix_sync(bf[ni], cB + (warp_n + ni * 16) * LDSA + ks, LDSA);
                    frag_to_tf32(bf[ni]);
                }
                #pragma unroll
                for (int mi = 0; mi < 4; mi++)
                    #pragma unroll
                    for (int ni = 0; ni < 2; ni++)
                        wmma::mma_sync(acc[mi][ni], af[mi], bf[ni], acc[mi][ni]);
            } else {
                wmma::fragment<wmma::matrix_b, 16, 16, 8, wmma::precision::tf32,
                               wmma::row_major> bf[2];
                #pragma unroll
                for (int ni = 0; ni < 2; ni++) {
                    wmma::load_matrix_sync(bf[ni], cB + ks * LDSB + warp_n + ni * 16, LDSB);
                    frag_to_tf32(bf[ni]);
                }
                #pragma unroll
                for (int mi = 0; mi < 4; mi++)
                    #pragma unroll
                    for (int ni = 0; ni < 2; ni++)
                        wmma::mma_sync(acc[mi][ni], af[mi], bf[ni], acc[mi][ni]);
            }
        }
        __syncthreads();
    }

    #pragma unroll
    for (int mi = 0; mi < 4; mi++)
        #pragma unroll
        for (int ni = 0; ni < 2; ni++) {
            size_t row = (size_t)(m0 + warp_m + mi * 16);
            int col = n0 + warp_n + ni * 16;
            wmma::store_matrix_sync(C + row * ldc + col, acc[mi][ni], ldc,
                                    wmma::mem_row_major);
        }
}

#define NT_SMEM ((4 * 128 * LDSA) * (int)sizeof(float))                    // 40960 B
#define NN_SMEM ((2 * 128 * LDSA + 2 * 16 * LDSB) * (int)sizeof(float))   // 37376 B

// ---------------- GEMM kernels -------------------------------------------------
__global__ __launch_bounds__(256, 2) void qkv_gemm_kernel(
    const float* __restrict__ X,
    const float* __restrict__ Wq,
    const float* __restrict__ Wk,
    const float* __restrict__ Wv)
{
    extern __shared__ float dynsm[];
    const float* W = (blockIdx.z == 0) ? Wq : (blockIdx.z == 1) ? Wk : Wv;
    float* C = g_qkv + (size_t)blockIdx.z * MN;
    gemm_body<true>(X, W, C, HID, HID, HID,
                    blockIdx.y * 128, blockIdx.x * 128, HID / BK, dynsm);
}

__global__ __launch_bounds__(256, 2) void out_gemm_kernel(
    const float* __restrict__ Wo, float* __restrict__ out)
{
    extern __shared__ float dynsm[];
    gemm_body<true>(g_attn_t, Wo, out, HID, HID, HID,
                    blockIdx.y * 128, blockIdx.x * 128, HID / BK, dynsm);
}

// scores[z,q,k] = Q[z,q,:] . K[z,k,:] ; skip blocks fully above the diagonal
__global__ __launch_bounds__(256, 2) void score_gemm_kernel()
{
    if (blockIdx.x > blockIdx.y) return;   // all k > all q in this block
    extern __shared__ float dynsm[];
    int z = blockIdx.z;
    const float* A = g_q + (size_t)z * SEQ * HD;
    const float* B = g_k + (size_t)z * SEQ * HD;
    float* C = g_scores + (size_t)z * SEQ * SEQ;
    gemm_body<true>(A, B, C, HD, HD, SEQ,
                    blockIdx.y * 128, blockIdx.x * 128, HD / BK, dynsm);
}

// O[z] = P[z] @ V[z] -> [B*S, H*D]; K-loop truncated at the causal diagonal
__global__ __launch_bounds__(256, 2) void pv_gemm_kernel()
{
    extern __shared__ float dynsm[];
    int z = blockIdx.z;
    int b = z / NH, h = z % NH;
    int m0 = blockIdx.y * 128;
    const float* A = g_scores + (size_t)z * SEQ * SEQ;   // [S,S] probs
    const float* B = g_v + (size_t)z * SEQ * HD;         // [S,HD]
    float* C = g_attn_t + (size_t)b * SEQ * HID + (size_t)h * HD;
    int kT = (m0 + 128) / BK;          // only k <= q contribute
    gemm_body<false>(A, B, C, SEQ, HD, HID, m0, 0, kT, dynsm);
}

// ---------------- RoPE + transpose to [B,H,S,D] (Round-3 verified) -------------
__global__ __launch_bounds__(256) void rope_transpose_kernel()
{
    long long idx = (long long)blockIdx.x * blockDim.x + threadIdx.x;
    const long long total = (long long)BSZ * NH * SEQ * 64;
    if (idx >= total) return;

    int d = (int)(idx % 64);  long long r = idx / 64;
    int s = (int)(r % SEQ);   r /= SEQ;
    int h = (int)(r % NH);
    int b = (int)(r / NH);

    double inv_freq = exp(-((double)(2 * d) / (double)HD) * log(10000.0));
    double ang = (double)s * inv_freq;
    double cd, sd;
    sincos(ang, &sd, &cd);
    float c  = (float)cd;
    float sn = (float)sd;

    size_t src = ((size_t)b * SEQ + s) * HID + (size_t)h * HD + d;   // [B*S, H*D]
    size_t dst = (((size_t)b * NH + h) * SEQ + s) * HD + d;          // [B,H,S,D]

    const float* Q0 = g_qkv;
    const float* K0 = g_qkv + MN;
    const float* V0 = g_qkv + 2 * MN;

    float q0 = Q0[src], q1 = Q0[src + 64];
    g_q[dst]      = q0 * c - q1 * sn;
    g_q[dst + 64] = q1 * c + q0 * sn;

    float k0 = K0[src], k1 = K0[src + 64];
    g_k[dst]      = k0 * c - k1 * sn;
    g_k[dst + 64] = k1 * c + k0 * sn;

    g_v[dst]      = V0[src];
    g_v[dst + 64] = V0[src + 64];
}

// ---------------- softmax (proven structure; __expf validated R8) --------------
__global__ __launch_bounds__(256) void softmax_kernel()
{
    const int warp = threadIdx.x >> 5;
    const int lane = threadIdx.x & 31;
    size_t row = (size_t)blockIdx.x * 8 + warp;            // 0 .. NZ*SEQ-1
    int q = (int)(row % SEQ);
    float* p = g_scores + row * (size_t)SEQ;
    const float scale = 0.08838834764831845f;              // 1/sqrt(128)

    float m = -INFINITY;
    for (int k = lane; k <= q; k += 32) m = fmaxf(m, p[k] * scale);
    #pragma unroll
    for (int o = 16; o; o >>= 1) m = fmaxf(m, __shfl_xor_sync(0xffffffffu, m, o));

    float ssum = 0.0f;
    for (int k = lane; k <= q; k += 32) ssum += __expf(p[k] * scale - m);
    #pragma unroll
    for (int o = 16; o; o >>= 1) ssum += __shfl_xor_sync(0xffffffffu, ssum, o);

    float inv = 1.0f / ssum;
    for (int k = lane; k < SEQ; k += 32)
        p[k] = (k <= q) ? __expf(p[k] * scale - m) * inv : 0.0f;
}

// ---------------- launch -------------------------------------------------------
extern "C" void kernel_launch(void* const* d_in, const int* in_sizes, int n_in,
                              void* d_out, int out_size)
{
    const float* X  = (const float*)d_in[0];
    const float* Wq = (const float*)d_in[1];
    const float* Wk = (const float*)d_in[2];
    const float* Wv = (const float*)d_in[3];
    const float* Wo = (const float*)d_in[4];
    float* out = (float*)d_out;

    cudaFuncSetAttribute(qkv_gemm_kernel,
                         cudaFuncAttributeMaxDynamicSharedMemorySize, NT_SMEM);
    cudaFuncSetAttribute(out_gemm_kernel,
                         cudaFuncAttributeMaxDynamicSharedMemorySize, NT_SMEM);
    cudaFuncSetAttribute(score_gemm_kernel,
                         cudaFuncAttributeMaxDynamicSharedMemorySize, NT_SMEM);
    cudaFuncSetAttribute(pv_gemm_kernel,
                         cudaFuncAttributeMaxDynamicSharedMemorySize, NN_SMEM);

    // 1. QKV projections
    {
        dim3 grid(HID / 128, MROWS / 128, 3);
        qkv_gemm_kernel<<<grid, 256, NT_SMEM>>>(X, Wq, Wk, Wv);
    }
    // 2. RoPE + transpose
    {
        long long total = (long long)BSZ * NH * SEQ * 64;  // 4,194,304
        rope_transpose_kernel<<<(unsigned)((total + 255) / 256), 256>>>();
    }
    // 3. Scores = Q K^T (lower-triangle blocks only)
    {
        dim3 grid(SEQ / 128, SEQ / 128, NZ);
        score_gemm_kernel<<<grid, 256, NT_SMEM>>>();
    }
    // 4. Softmax
    {
        unsigned rows = NZ * SEQ;                 // 65536
        softmax_kernel<<<rows / 8, 256>>>();
    }
    // 5. O = P V
    {
        dim3 grid(1, SEQ / 128, NZ);
        pv_gemm_kernel<<<grid, 256, NN_SMEM>>>();
    }
    // 6. Output projection
    {
        dim3 grid(HID / 128, MROWS / 128);
        out_gemm_kernel<<<grid, 256, NT_SMEM>>>(Wo, out);
    }
}

// round 10
// speedup vs baseline: 1.1640x; 1.0153x over previous
#include <cuda_runtime.h>
#include <cuda_bf16.h>
#include <math.h>
#include <stdint.h>
#include <mma.h>

using namespace nvcuda;

// Problem constants
#define BSZ   2
#define SEQ   2048
#define NH    16
#define HD    128
#define HID   2048
#define MROWS (BSZ*SEQ)           // 4096
#define MN    ((size_t)MROWS*HID) // 8388608
#define NZ    (BSZ*NH)            // 32 (b,h) pairs
#define WELEM (HID*HID)           // 4194304 per weight

#define BK    16
#define LDSA  20                  // smem ld for [row][k] tiles (BK=16 + pad)
#define LDSB  132                 // smem ld for [k][n] tiles (NN)
#define NSTG  3                   // cp.async pipeline stages

// ---------------- scratch (device globals; no allocation allowed) -------------
__device__ float g_x [MN];                      // tf32-rounded hidden states
__device__ float g_wq[WELEM];                   // tf32-rounded weights
__device__ float g_wk[WELEM];
__device__ float g_wv[WELEM];
__device__ float g_wo[WELEM];
__device__ float g_qkv[3*MROWS*HID];            // raw Q,K,V projections (fp32)
__device__ float g_q[MROWS*HID];                // [B,H,S,D] after RoPE (tf32-rounded)
__device__ float g_k[MROWS*HID];
__device__ float g_v[MROWS*HID];
__device__ float g_attn_t[MROWS*HID];           // attention out [B*S, H*D] (tf32-rounded)
__device__ float g_scores[(size_t)NZ*SEQ*SEQ];  // [B*H, S, S] scores / probs

// ---------------- cp.async helpers --------------------------------------------
__device__ __forceinline__ void cp16(void* smem_dst, const void* gsrc) {
    uint32_t s = (uint32_t)__cvta_generic_to_shared(smem_dst);
    asm volatile("cp.async.cg.shared.global [%0], [%1], 16;" :: "r"(s), "l"(gsrc));
}
#define CP_COMMIT() asm volatile("cp.async.commit_group;")
#define CP_WAIT1()  asm volatile("cp.async.wait_group 1;")

template <class Frag>
__device__ __forceinline__ void frag_to_tf32(Frag& f) {
    #pragma unroll
    for (int e = 0; e < f.num_elements; e++)
        f.x[e] = wmma::__float_to_tf32(f.x[e]);
}

// ---------------- tf32 pre-rounding pass ---------------------------------------
__global__ __launch_bounds__(256) void round_kernel(const float4* __restrict__ src,
                                                    int n4, int which)
{
    int i = blockIdx.x * blockDim.x + threadIdx.x;
    if (i >= n4) return;
    float4* dst = (which == 0) ? (float4*)g_x
                : (which == 1) ? (float4*)g_wq
                : (which == 2) ? (float4*)g_wk
                : (which == 3) ? (float4*)g_wv
                               : (float4*)g_wo;
    float4 v = src[i];
    v.x = wmma::__float_to_tf32(v.x);
    v.y = wmma::__float_to_tf32(v.y);
    v.z = wmma::__float_to_tf32(v.z);
    v.w = wmma::__float_to_tf32(v.w);
    dst[i] = v;
}

// =====================================================================
// WMMA tf32 GEMM, cp.async 3-stage pipeline, 2 CTAs/SM.
// Block tile 128x128, BK=16, 256 threads (8 warps 2x4), warp 64x32.
// Operands are PRE-ROUNDED to tf32 — no cvt in the inner loop.
//  - TRANSB=true : B is [N,K] row-major (C = A * B^T)
//  - TRANSB=false: B is [K,N] row-major (C = A * B)
// ROUND_C: round accumulator to tf32 before store (for chained GEMMs).
// =====================================================================
template <bool TRANSB, bool ROUND_C>
__device__ __forceinline__ void gemm_body(
    const float* __restrict__ A, const float* __restrict__ B, float* __restrict__ C,
    int lda, int ldb, int ldc, int m0, int n0, int kTiles, float* dynsm)
{
    float* smA = dynsm;                           // [NSTG][128*LDSA]
    float* smB = dynsm + NSTG * 128 * LDSA;       // [NSTG][128*LDSA] or [NSTG][16*LDSB]

    const int tid = threadIdx.x;
    const int wid = tid >> 5;
    const int warp_m = (wid >> 2) * 64;
    const int warp_n = (wid & 3) * 32;

    wmma::fragment<wmma::accumulator, 16, 16, 8, float> acc[4][2];
    #pragma unroll
    for (int mi = 0; mi < 4; mi++)
        #pragma unroll
        for (int ni = 0; ni < 2; ni++)
            wmma::fill_fragment(acc[mi][ni], 0.0f);

    auto issue = [&](int kt) {
        const int stg = kt % NSTG;
        const int k0 = kt * BK;
        float* dA = smA + stg * 128 * LDSA;
        #pragma unroll
        for (int r = 0; r < 2; r++) {
            int idx = tid + r * 256;       // 0..511 float4s (128 rows x 4)
            int row = idx >> 2;            // 0..127
            int c4  = (idx & 3) << 2;      // 0,4,8,12
            cp16(dA + row * LDSA + c4, A + (size_t)(m0 + row) * lda + k0 + c4);
        }
        if (TRANSB) {
            float* dB = smB + stg * 128 * LDSA;
            #pragma unroll
            for (int r = 0; r < 2; r++) {
                int idx = tid + r * 256;
                int row = idx >> 2;
                int c4  = (idx & 3) << 2;
                cp16(dB + row * LDSA + c4, B + (size_t)(n0 + row) * ldb + k0 + c4);
            }
        } else {
            float* dB = smB + stg * 16 * LDSB;
            #pragma unroll
            for (int r = 0; r < 2; r++) {
                int idx = tid + r * 256;       // 0..511 (16 krows x 32)
                int krow = idx >> 5;           // 0..15
                int c4   = (idx & 31) << 2;    // 0..124
                cp16(dB + krow * LDSB + c4, B + (size_t)(k0 + krow) * ldb + n0 + c4);
            }
        }
        CP_COMMIT();
    };

    issue(0);
    if (kTiles > 1) issue(1);
    for (int kt = 0; kt < kTiles; kt++) {
        CP_WAIT1();            // stage kt complete (kt+1 may be in flight)
        __syncthreads();       // also guards stage-buffer reuse
        if (kt + 2 < kTiles) issue(kt + 2);
        const int stg = kt % NSTG;
        const float* cA = smA + stg * 128 * LDSA;
        const float* cB = TRANSB ? (smB + stg * 128 * LDSA) : (smB + stg * 16 * LDSB);

        #pragma unroll
        for (int ks = 0; ks < BK; ks += 8) {
            wmma::fragment<wmma::matrix_a, 16, 16, 8, wmma::precision::tf32,
                           wmma::row_major> af[4];
            #pragma unroll
            for (int mi = 0; mi < 4; mi++)
                wmma::load_matrix_sync(af[mi], cA + (warp_m + mi * 16) * LDSA + ks, LDSA);
            if (TRANSB) {
                wmma::fragment<wmma::matrix_b, 16, 16, 8, wmma::precision::tf32,
                               wmma::col_major> bf[2];
                #pragma unroll
                for (int ni = 0; ni < 2; ni++)
                    wmma::load_matrix_sync(bf[ni], cB + (warp_n + ni * 16) * LDSA + ks, LDSA);
                #pragma unroll
                for (int mi = 0; mi < 4; mi++)
                    #pragma unroll
                    for (int ni = 0; ni < 2; ni++)
                        wmma::mma_sync(acc[mi][ni], af[mi], bf[ni], acc[mi][ni]);
            } else {
                wmma::fragment<wmma::matrix_b, 16, 16, 8, wmma::precision::tf32,
                               wmma::row_major> bf[2];
                #pragma unroll
                for (int ni = 0; ni < 2; ni++)
                    wmma::load_matrix_sync(bf[ni], cB + ks * LDSB + warp_n + ni * 16, LDSB);
                #pragma unroll
                for (int mi = 0; mi < 4; mi++)
                    #pragma unroll
                    for (int ni = 0; ni < 2; ni++)
                        wmma::mma_sync(acc[mi][ni], af[mi], bf[ni], acc[mi][ni]);
            }
        }
    }

    #pragma unroll
    for (int mi = 0; mi < 4; mi++)
        #pragma unroll
        for (int ni = 0; ni < 2; ni++) {
            if (ROUND_C) frag_to_tf32(acc[mi][ni]);
            size_t row = (size_t)(m0 + warp_m + mi * 16);
            int col = n0 + warp_n + ni * 16;
            wmma::store_matrix_sync(C + row * ldc + col, acc[mi][ni], ldc,
                                    wmma::mem_row_major);
        }
}

#define NT_SMEM ((2 * NSTG * 128 * LDSA) * (int)sizeof(float))                       // 61440 B
#define NN_SMEM ((NSTG * 128 * LDSA + NSTG * 16 * LDSB) * (int)sizeof(float))        // 56064 B

// ---------------- GEMM kernels -------------------------------------------------
__global__ __launch_bounds__(256, 2) void qkv_gemm_kernel()
{
    extern __shared__ float dynsm[];
    const float* W = (blockIdx.z == 0) ? g_wq : (blockIdx.z == 1) ? g_wk : g_wv;
    float* C = g_qkv + (size_t)blockIdx.z * MN;
    gemm_body<true, false>(g_x, W, C, HID, HID, HID,
                           blockIdx.y * 128, blockIdx.x * 128, HID / BK, dynsm);
}

__global__ __launch_bounds__(256, 2) void out_gemm_kernel(float* __restrict__ out)
{
    extern __shared__ float dynsm[];
    gemm_body<true, false>(g_attn_t, g_wo, out, HID, HID, HID,
                           blockIdx.y * 128, blockIdx.x * 128, HID / BK, dynsm);
}

// scores[z,q,k] = Q[z,q,:] . K[z,k,:] ; skip blocks fully above the diagonal
__global__ __launch_bounds__(256, 2) void score_gemm_kernel()
{
    if (blockIdx.x > blockIdx.y) return;   // all k > all q in this block
    extern __shared__ float dynsm[];
    int z = blockIdx.z;
    const float* A = g_q + (size_t)z * SEQ * HD;
    const float* B = g_k + (size_t)z * SEQ * HD;
    float* C = g_scores + (size_t)z * SEQ * SEQ;
    gemm_body<true, false>(A, B, C, HD, HD, SEQ,
                           blockIdx.y * 128, blockIdx.x * 128, HD / BK, dynsm);
}

// O[z] = P[z] @ V[z] -> [B*S, H*D]; K-loop truncated at the causal diagonal.
// C rounded to tf32 (consumed as A by the out-projection).
__global__ __launch_bounds__(256, 2) void pv_gemm_kernel()
{
    extern __shared__ float dynsm[];
    int z = blockIdx.z;
    int b = z / NH, h = z % NH;
    int m0 = blockIdx.y * 128;
    const float* A = g_scores + (size_t)z * SEQ * SEQ;   // [S,S] probs (pre-rounded)
    const float* B = g_v + (size_t)z * SEQ * HD;         // [S,HD]   (pre-rounded)
    float* C = g_attn_t + (size_t)b * SEQ * HID + (size_t)h * HD;
    int kT = (m0 + 128) / BK;          // only k <= q contribute
    gemm_body<false, true>(A, B, C, SEQ, HD, HID, m0, 0, kT, dynsm);
}

// ---------------- RoPE + transpose to [B,H,S,D]; writes tf32-rounded -----------
__global__ __launch_bounds__(256) void rope_transpose_kernel()
{
    long long idx = (long long)blockIdx.x * blockDim.x + threadIdx.x;
    const long long total = (long long)BSZ * NH * SEQ * 64;
    if (idx >= total) return;

    int d = (int)(idx % 64);  long long r = idx / 64;
    int s = (int)(r % SEQ);   r /= SEQ;
    int h = (int)(r % NH);
    int b = (int)(r / NH);

    double inv_freq = exp(-((double)(2 * d) / (double)HD) * log(10000.0));
    double ang = (double)s * inv_freq;
    double cd, sd;
    sincos(ang, &sd, &cd);
    float c  = (float)cd;
    float sn = (float)sd;

    size_t src = ((size_t)b * SEQ + s) * HID + (size_t)h * HD + d;   // [B*S, H*D]
    size_t dst = (((size_t)b * NH + h) * SEQ + s) * HD + d;          // [B,H,S,D]

    const float* Q0 = g_qkv;
    const float* K0 = g_qkv + MN;
    const float* V0 = g_qkv + 2 * MN;

    float q0 = Q0[src], q1 = Q0[src + 64];
    g_q[dst]      = wmma::__float_to_tf32(q0 * c - q1 * sn);
    g_q[dst + 64] = wmma::__float_to_tf32(q1 * c + q0 * sn);

    float k0 = K0[src], k1 = K0[src + 64];
    g_k[dst]      = wmma::__float_to_tf32(k0 * c - k1 * sn);
    g_k[dst + 64] = wmma::__float_to_tf32(k1 * c + k0 * sn);

    g_v[dst]      = wmma::__float_to_tf32(V0[src]);
    g_v[dst + 64] = wmma::__float_to_tf32(V0[src + 64]);
}

// ---------------- softmax; writes tf32-rounded probs ---------------------------
// Zero-fill only up to the 128-aligned block boundary PV actually reads.
__global__ __launch_bounds__(256) void softmax_kernel()
{
    const int warp = threadIdx.x >> 5;
    const int lane = threadIdx.x & 31;
    size_t row = (size_t)blockIdx.x * 8 + warp;            // 0 .. NZ*SEQ-1
    int q = (int)(row % SEQ);
    float* p = g_scores + row * (size_t)SEQ;
    const float scale = 0.08838834764831845f;              // 1/sqrt(128)

    float m = -INFINITY;
    for (int k = lane; k <= q; k += 32) m = fmaxf(m, p[k] * scale);
    #pragma unroll
    for (int o = 16; o; o >>= 1) m = fmaxf(m, __shfl_xor_sync(0xffffffffu, m, o));

    float ssum = 0.0f;
    for (int k = lane; k <= q; k += 32) ssum += __expf(p[k] * scale - m);
    #pragma unroll
    for (int o = 16; o; o >>= 1) ssum += __shfl_xor_sync(0xffffffffu, ssum, o);

    float inv = 1.0f / ssum;
    int kmax = ((q >> 7) + 1) << 7;    // PV reads k < kmax for this row's block
    for (int k = lane; k < kmax; k += 32)
        p[k] = (k <= q) ? wmma::__float_to_tf32(__expf(p[k] * scale - m) * inv) : 0.0f;
}

// ---------------- launch -------------------------------------------------------
extern "C" void kernel_launch(void* const* d_in, const int* in_sizes, int n_in,
                              void* d_out, int out_size)
{
    const float* X  = (const float*)d_in[0];
    const float* Wq = (const float*)d_in[1];
    const float* Wk = (const float*)d_in[2];
    const float* Wv = (const float*)d_in[3];
    const float* Wo = (const float*)d_in[4];
    float* out = (float*)d_out;

    cudaFuncSetAttribute(qkv_gemm_kernel,
                         cudaFuncAttributeMaxDynamicSharedMemorySize, NT_SMEM);
    cudaFuncSetAttribute(out_gemm_kernel,
                         cudaFuncAttributeMaxDynamicSharedMemorySize, NT_SMEM);
    cudaFuncSetAttribute(score_gemm_kernel,
                         cudaFuncAttributeMaxDynamicSharedMemorySize, NT_SMEM);
    cudaFuncSetAttribute(pv_gemm_kernel,
                         cudaFuncAttributeMaxDynamicSharedMemorySize, NN_SMEM);

    // 0. Pre-round X and weights to tf32
    round_kernel<<<(MN/4 + 255) / 256, 256>>>((const float4*)X,  MN/4,    0);
    round_kernel<<<(WELEM/4 + 255) / 256, 256>>>((const float4*)Wq, WELEM/4, 1);
    round_kernel<<<(WELEM/4 + 255) / 256, 256>>>((const float4*)Wk, WELEM/4, 2);
    round_kernel<<<(WELEM/4 + 255) / 256, 256>>>((const float4*)Wv, WELEM/4, 3);
    round_kernel<<<(WELEM/4 + 255) / 256, 256>>>((const float4*)Wo, WELEM/4, 4);

    // 1. QKV projections
    {
        dim3 grid(HID / 128, MROWS / 128, 3);
        qkv_gemm_kernel<<<grid, 256, NT_SMEM>>>();
    }
    // 2. RoPE + transpose
    {
        long long total = (long long)BSZ * NH * SEQ * 64;  // 4,194,304
        rope_transpose_kernel<<<(unsigned)((total + 255) / 256), 256>>>();
    }
    // 3. Scores = Q K^T (lower-triangle blocks only)
    {
        dim3 grid(SEQ / 128, SEQ / 128, NZ);
        score_gemm_kernel<<<grid, 256, NT_SMEM>>>();
    }
    // 4. Softmax
    {
        unsigned rows = NZ * SEQ;                 // 65536
        softmax_kernel<<<rows / 8, 256>>>();
    }
    // 5. O = P V
    {
        dim3 grid(1, SEQ / 128, NZ);
        pv_gemm_kernel<<<grid, 256, NN_SMEM>>>();
    }
    // 6. Output projection
    {
        dim3 grid(HID / 128, MROWS / 128);
        out_gemm_kernel<<<grid, 256, NT_SMEM>>>(out);
    }
}

// round 13
// speedup vs baseline: 1.1908x; 1.0230x over previous
#include <cuda_runtime.h>
#include <cuda_bf16.h>
#include <math.h>
#include <stdint.h>
#include <mma.h>

using namespace nvcuda;

// Problem constants
#define BSZ   2
#define SEQ   2048
#define NH    16
#define HD    128
#define HID   2048
#define MROWS (BSZ*SEQ)           // 4096
#define MN    ((size_t)MROWS*HID) // 8388608
#define NZ    (BSZ*NH)            // 32 (b,h) pairs
#define WELEM (HID*HID)           // 4194304 per weight

#define BK    32
#define LDSA  36                  // smem ld for [row][k] tiles (BK=32 + pad)
#define LDSB  132                 // smem ld for [k][n] tiles (NN)
#define NSTG  3                   // cp.async pipeline stages

// ---------------- scratch (device globals; no allocation allowed) -------------
__device__ float g_x [MN];                      // tf32-rounded hidden states
__device__ float g_wq[WELEM];                   // tf32-rounded weights
__device__ float g_wk[WELEM];
__device__ float g_wv[WELEM];
__device__ float g_wo[WELEM];
__device__ float g_qkv[3*MROWS*HID];            // raw Q,K,V projections (fp32)
__device__ float g_q[MROWS*HID];                // [B,H,S,D] after RoPE (tf32-rounded)
__device__ float g_k[MROWS*HID];
__device__ float g_v[MROWS*HID];
__device__ float g_attn_t[MROWS*HID];           // attention out [B*S, H*D] (tf32-rounded)
__device__ float g_scores[(size_t)NZ*SEQ*SEQ];  // [B*H, S, S] scores / probs

// ---------------- cp.async helpers --------------------------------------------
__device__ __forceinline__ void cp16(void* smem_dst, const void* gsrc) {
    uint32_t s = (uint32_t)__cvta_generic_to_shared(smem_dst);
    asm volatile("cp.async.cg.shared.global [%0], [%1], 16;" :: "r"(s), "l"(gsrc));
}
#define CP_COMMIT() asm volatile("cp.async.commit_group;")
#define CP_WAIT1()  asm volatile("cp.async.wait_group 1;")

template <class Frag>
__device__ __forceinline__ void frag_to_tf32(Frag& f) {
    #pragma unroll
    for (int e = 0; e < f.num_elements; e++)
        f.x[e] = wmma::__float_to_tf32(f.x[e]);
}

// ---------------- tf32 pre-rounding pass ---------------------------------------
__global__ __launch_bounds__(256) void round_kernel(const float4* __restrict__ src,
                                                    int n4, int which)
{
    int i = blockIdx.x * blockDim.x + threadIdx.x;
    if (i >= n4) return;
    float4* dst = (which == 0) ? (float4*)g_x
                : (which == 1) ? (float4*)g_wq
                : (which == 2) ? (float4*)g_wk
                : (which == 3) ? (float4*)g_wv
                               : (float4*)g_wo;
    float4 v = src[i];
    v.x = wmma::__float_to_tf32(v.x);
    v.y = wmma::__float_to_tf32(v.y);
    v.z = wmma::__float_to_tf32(v.z);
    v.w = wmma::__float_to_tf32(v.w);
    dst[i] = v;
}

// =====================================================================
// WMMA tf32 GEMM, cp.async 3-stage pipeline, 2 CTAs/SM, BK=32.
// Block tile 128x128, 256 threads (8 warps 2x4), warp 64x32.
// Operands PRE-ROUNDED to tf32 — no cvt in the inner loop.
//  - TRANSB=true : B is [N,K] row-major (C = A * B^T)
//  - TRANSB=false: B is [K,N] row-major (C = A * B)
// ROUND_C: round accumulator to tf32 before store (chained GEMMs).
// =====================================================================
template <bool TRANSB, bool ROUND_C>
__device__ __forceinline__ void gemm_body(
    const float* __restrict__ A, const float* __restrict__ B, float* __restrict__ C,
    int lda, int ldb, int ldc, int m0, int n0, int kTiles, float* dynsm)
{
    float* smA = dynsm;                           // [NSTG][128*LDSA]
    float* smB = dynsm + NSTG * 128 * LDSA;       // [NSTG][128*LDSA] or [NSTG][32*LDSB]

    const int tid = threadIdx.x;
    const int wid = tid >> 5;
    const int warp_m = (wid >> 2) * 64;
    const int warp_n = (wid & 3) * 32;

    wmma::fragment<wmma::accumulator, 16, 16, 8, float> acc[4][2];
    #pragma unroll
    for (int mi = 0; mi < 4; mi++)
        #pragma unroll
        for (int ni = 0; ni < 2; ni++)
            wmma::fill_fragment(acc[mi][ni], 0.0f);

    auto issue = [&](int kt) {
        const int stg = kt % NSTG;
        const int k0 = kt * BK;
        float* dA = smA + stg * 128 * LDSA;
        #pragma unroll
        for (int r = 0; r < 4; r++) {
            int idx = tid + r * 256;       // 0..1023 float4s (128 rows x 8)
            int row = idx >> 3;            // 0..127
            int c4  = (idx & 7) << 2;      // 0..28
            cp16(dA + row * LDSA + c4, A + (size_t)(m0 + row) * lda + k0 + c4);
        }
        if (TRANSB) {
            float* dB = smB + stg * 128 * LDSA;
            #pragma unroll
            for (int r = 0; r < 4; r++) {
                int idx = tid + r * 256;
                int row = idx >> 3;
                int c4  = (idx & 7) << 2;
                cp16(dB + row * LDSA + c4, B + (size_t)(n0 + row) * ldb + k0 + c4);
            }
        } else {
            float* dB = smB + stg * 32 * LDSB;
            #pragma unroll
            for (int r = 0; r < 4; r++) {
                int idx = tid + r * 256;       // 0..1023 (32 krows x 32)
                int krow = idx >> 5;           // 0..31
                int c4   = (idx & 31) << 2;    // 0..124
                cp16(dB + krow * LDSB + c4, B + (size_t)(k0 + krow) * ldb + n0 + c4);
            }
        }
        CP_COMMIT();
    };

    issue(0);
    if (kTiles > 1) issue(1);
    for (int kt = 0; kt < kTiles; kt++) {
        CP_WAIT1();            // stage kt complete (kt+1 may be in flight)
        __syncthreads();       // also guards stage-buffer reuse
        if (kt + 2 < kTiles) issue(kt + 2);
        const int stg = kt % NSTG;
        const float* cA = smA + stg * 128 * LDSA;
        const float* cB = TRANSB ? (smB + stg * 128 * LDSA) : (smB + stg * 32 * LDSB);

        #pragma unroll
        for (int ks = 0; ks < BK; ks += 8) {
            wmma::fragment<wmma::matrix_a, 16, 16, 8, wmma::precision::tf32,
                           wmma::row_major> af[4];
            #pragma unroll
            for (int mi = 0; mi < 4; mi++)
                wmma::load_matrix_sync(af[mi], cA + (warp_m + mi * 16) * LDSA + ks, LDSA);
            if (TRANSB) {
                wmma::fragment<wmma::matrix_b, 16, 16, 8, wmma::precision::tf32,
                               wmma::col_major> bf[2];
                #pragma unroll
                for (int ni = 0; ni < 2; ni++)
                    wmma::load_matrix_sync(bf[ni], cB + (warp_n + ni * 16) * LDSA + ks, LDSA);
                #pragma unroll
                for (int mi = 0; mi < 4; mi++)
                    #pragma unroll
                    for (int ni = 0; ni < 2; ni++)
                        wmma::mma_sync(acc[mi][ni], af[mi], bf[ni], acc[mi][ni]);
            } else {
                wmma::fragment<wmma::matrix_b, 16, 16, 8, wmma::precision::tf32,
                               wmma::row_major> bf[2];
                #pragma unroll
                for (int ni = 0; ni < 2; ni++)
                    wmma::load_matrix_sync(bf[ni], cB + ks * LDSB + warp_n + ni * 16, LDSB);
                #pragma unroll
                for (int mi = 0; mi < 4; mi++)
                    #pragma unroll
                    for (int ni = 0; ni < 2; ni++)
                        wmma::mma_sync(acc[mi][ni], af[mi], bf[ni], acc[mi][ni]);
            }
        }
    }

    #pragma unroll
    for (int mi = 0; mi < 4; mi++)
        #pragma unroll
        for (int ni = 0; ni < 2; ni++) {
            if (ROUND_C) frag_to_tf32(acc[mi][ni]);
            size_t row = (size_t)(m0 + warp_m + mi * 16);
            int col = n0 + warp_n + ni * 16;
            wmma::store_matrix_sync(C + row * ldc + col, acc[mi][ni], ldc,
                                    wmma::mem_row_major);
        }
}

#define NT_SMEM ((2 * NSTG * 128 * LDSA) * (int)sizeof(float))                 // 110592 B
#define NN_SMEM ((NSTG * 128 * LDSA + NSTG * 32 * LDSB) * (int)sizeof(float))  // 105984 B

// ---------------- GEMM kernels -------------------------------------------------
__global__ __launch_bounds__(256, 2) void qkv_gemm_kernel()
{
    extern __shared__ float dynsm[];
    const float* W = (blockIdx.z == 0) ? g_wq : (blockIdx.z == 1) ? g_wk : g_wv;
    float* C = g_qkv + (size_t)blockIdx.z * MN;
    gemm_body<true, false>(g_x, W, C, HID, HID, HID,
                           blockIdx.y * 128, blockIdx.x * 128, HID / BK, dynsm);
}

__global__ __launch_bounds__(256, 2) void out_gemm_kernel(float* __restrict__ out)
{
    extern __shared__ float dynsm[];
    gemm_body<true, false>(g_attn_t, g_wo, out, HID, HID, HID,
                           blockIdx.y * 128, blockIdx.x * 128, HID / BK, dynsm);
}

// scores[z,q,k] = Q[z,q,:] . K[z,k,:] ; skip blocks fully above the diagonal
__global__ __launch_bounds__(256, 2) void score_gemm_kernel()
{
    if (blockIdx.x > blockIdx.y) return;   // all k > all q in this block
    extern __shared__ float dynsm[];
    int z = blockIdx.z;
    const float* A = g_q + (size_t)z * SEQ * HD;
    const float* B = g_k + (size_t)z * SEQ * HD;
    float* C = g_scores + (size_t)z * SEQ * SEQ;
    gemm_body<true, false>(A, B, C, HD, HD, SEQ,
                           blockIdx.y * 128, blockIdx.x * 128, HD / BK, dynsm);
}

// O[z] = P[z] @ V[z] -> [B*S, H*D]; K-loop truncated at the causal diagonal.
// C rounded to tf32 (consumed as A by the out-projection).
__global__ __launch_bounds__(256, 2) void pv_gemm_kernel()
{
    extern __shared__ float dynsm[];
    int z = blockIdx.z;
    int b = z / NH, h = z % NH;
    int m0 = blockIdx.y * 128;
    const float* A = g_scores + (size_t)z * SEQ * SEQ;   // [S,S] probs (pre-rounded)
    const float* B = g_v + (size_t)z * SEQ * HD;         // [S,HD]   (pre-rounded)
    float* C = g_attn_t + (size_t)b * SEQ * HID + (size_t)h * HD;
    int kT = (m0 + 128) / BK;          // only k <= q contribute
    gemm_body<false, true>(A, B, C, SEQ, HD, HID, m0, 0, kT, dynsm);
}

// ---------------- RoPE + transpose to [B,H,S,D]; writes tf32-rounded -----------
__global__ __launch_bounds__(256) void rope_transpose_kernel()
{
    long long idx = (long long)blockIdx.x * blockDim.x + threadIdx.x;
    const long long total = (long long)BSZ * NH * SEQ * 64;
    if (idx >= total) return;

    int d = (int)(idx % 64);  long long r = idx / 64;
    int s = (int)(r % SEQ);   r /= SEQ;
    int h = (int)(r % NH);
    int b = (int)(r / NH);

    double inv_freq = exp(-((double)(2 * d) / (double)HD) * log(10000.0));
    double ang = (double)s * inv_freq;
    double cd, sd;
    sincos(ang, &sd, &cd);
    float c  = (float)cd;
    float sn = (float)sd;

    size_t src = ((size_t)b * SEQ + s) * HID + (size_t)h * HD + d;   // [B*S, H*D]
    size_t dst = (((size_t)b * NH + h) * SEQ + s) * HD + d;          // [B,H,S,D]

    const float* Q0 = g_qkv;
    const float* K0 = g_qkv + MN;
    const float* V0 = g_qkv + 2 * MN;

    float q0 = Q0[src], q1 = Q0[src + 64];
    g_q[dst]      = wmma::__float_to_tf32(q0 * c - q1 * sn);
    g_q[dst + 64] = wmma::__float_to_tf32(q1 * c + q0 * sn);

    float k0 = K0[src], k1 = K0[src + 64];
    g_k[dst]      = wmma::__float_to_tf32(k0 * c - k1 * sn);
    g_k[dst + 64] = wmma::__float_to_tf32(k1 * c + k0 * sn);

    g_v[dst]      = wmma::__float_to_tf32(V0[src]);
    g_v[dst + 64] = wmma::__float_to_tf32(V0[src + 64]);
}

// ---------------- softmax; writes tf32-rounded probs ---------------------------
// Zero-fill only up to the 128-aligned block boundary PV actually reads.
__global__ __launch_bounds__(256) void softmax_kernel()
{
    const int warp = threadIdx.x >> 5;
    const int lane = threadIdx.x & 31;
    size_t row = (size_t)blockIdx.x * 8 + warp;            // 0 .. NZ*SEQ-1
    int q = (int)(row % SEQ);
    float* p = g_scores + row * (size_t)SEQ;
    const float scale = 0.08838834764831845f;              // 1/sqrt(128)

    float m = -INFINITY;
    for (int k = lane; k <= q; k += 32) m = fmaxf(m, p[k] * scale);
    #pragma unroll
    for (int o = 16; o; o >>= 1) m = fmaxf(m, __shfl_xor_sync(0xffffffffu, m, o));

    float ssum = 0.0f;
    for (int k = lane; k <= q; k += 32) ssum += __expf(p[k] * scale - m);
    #pragma unroll
    for (int o = 16; o; o >>= 1) ssum += __shfl_xor_sync(0xffffffffu, ssum, o);

    float inv = 1.0f / ssum;
    int kmax = ((q >> 7) + 1) << 7;    // PV reads k < kmax for this row's block
    for (int k = lane; k < kmax; k += 32)
        p[k] = (k <= q) ? wmma::__float_to_tf32(__expf(p[k] * scale - m) * inv) : 0.0f;
}

// ---------------- launch -------------------------------------------------------
extern "C" void kernel_launch(void* const* d_in, const int* in_sizes, int n_in,
                              void* d_out, int out_size)
{
    const float* X  = (const float*)d_in[0];
    const float* Wq = (const float*)d_in[1];
    const float* Wk = (const float*)d_in[2];
    const float* Wv = (const float*)d_in[3];
    const float* Wo = (const float*)d_in[4];
    float* out = (float*)d_out;

    cudaFuncSetAttribute(qkv_gemm_kernel,
                         cudaFuncAttributeMaxDynamicSharedMemorySize, NT_SMEM);
    cudaFuncSetAttribute(out_gemm_kernel,
                         cudaFuncAttributeMaxDynamicSharedMemorySize, NT_SMEM);
    cudaFuncSetAttribute(score_gemm_kernel,
                         cudaFuncAttributeMaxDynamicSharedMemorySize, NT_SMEM);
    cudaFuncSetAttribute(pv_gemm_kernel,
                         cudaFuncAttributeMaxDynamicSharedMemorySize, NN_SMEM);

    // 0. Pre-round X and weights to tf32
    round_kernel<<<(MN/4 + 255) / 256, 256>>>((const float4*)X,  MN/4,    0);
    round_kernel<<<(WELEM/4 + 255) / 256, 256>>>((const float4*)Wq, WELEM/4, 1);
    round_kernel<<<(WELEM/4 + 255) / 256, 256>>>((const float4*)Wk, WELEM/4, 2);
    round_kernel<<<(WELEM/4 + 255) / 256, 256>>>((const float4*)Wv, WELEM/4, 3);
    round_kernel<<<(WELEM/4 + 255) / 256, 256>>>((const float4*)Wo, WELEM/4, 4);

    // 1. QKV projections
    {
        dim3 grid(HID / 128, MROWS / 128, 3);
        qkv_gemm_kernel<<<grid, 256, NT_SMEM>>>();
    }
    // 2. RoPE + transpose
    {
        long long total = (long long)BSZ * NH * SEQ * 64;  // 4,194,304
        rope_transpose_kernel<<<(unsigned)((total + 255) / 256), 256>>>();
    }
    // 3. Scores = Q K^T (lower-triangle blocks only)
    {
        dim3 grid(SEQ / 128, SEQ / 128, NZ);
        score_gemm_kernel<<<grid, 256, NT_SMEM>>>();
    }
    // 4. Softmax
    {
        unsigned rows = NZ * SEQ;                 // 65536
        softmax_kernel<<<rows / 8, 256>>>();
    }
    // 5. O = P V
    {
        dim3 grid(1, SEQ / 128, NZ);
        pv_gemm_kernel<<<grid, 256, NN_SMEM>>>();
    }
    // 6. Output projection
    {
        dim3 grid(HID / 128, MROWS / 128);
        out_gemm_kernel<<<grid, 256, NT_SMEM>>>(out);
    }
}

// round 14
// speedup vs baseline: 1.2607x; 1.0587x over previous
#include <cuda_runtime.h>
#include <cuda_bf16.h>
#include <math.h>
#include <stdint.h>
#include <mma.h>

using namespace nvcuda;

// Problem constants
#define BSZ   2
#define SEQ   2048
#define NH    16
#define HD    128
#define HID   2048
#define MROWS (BSZ*SEQ)           // 4096
#define MN    ((size_t)MROWS*HID) // 8388608
#define NZ    (BSZ*NH)            // 32 (b,h) pairs
#define WELEM (HID*HID)           // 4194304 per weight

#define BK    32
#define LDSA  36                  // smem ld for [row][k] tiles (BK=32 + pad)
#define LDSB  132                 // smem ld for [k][n] tiles (NN)
#define NSTG  3                   // cp.async pipeline stages
#define NTHR  128                 // 4 warps (2x2), warp tile 64x64

// ---------------- scratch (device globals; no allocation allowed) -------------
__device__ float g_x [MN];                      // tf32-rounded hidden states
__device__ float g_wq[WELEM];                   // tf32-rounded weights
__device__ float g_wk[WELEM];
__device__ float g_wv[WELEM];
__device__ float g_wo[WELEM];
__device__ float g_qkv[3*MROWS*HID];            // raw Q,K,V projections (fp32)
__device__ float g_q[MROWS*HID];                // [B,H,S,D] after RoPE (tf32-rounded)
__device__ float g_k[MROWS*HID];
__device__ float g_v[MROWS*HID];
__device__ float g_attn_t[MROWS*HID];           // attention out [B*S, H*D] (tf32-rounded)
__device__ float g_scores[(size_t)NZ*SEQ*SEQ];  // [B*H, S, S] scores / probs

// ---------------- cp.async helpers --------------------------------------------
__device__ __forceinline__ void cp16(void* smem_dst, const void* gsrc) {
    uint32_t s = (uint32_t)__cvta_generic_to_shared(smem_dst);
    asm volatile("cp.async.cg.shared.global [%0], [%1], 16;" :: "r"(s), "l"(gsrc));
}
#define CP_COMMIT() asm volatile("cp.async.commit_group;")
#define CP_WAIT1()  asm volatile("cp.async.wait_group 1;")

template <class Frag>
__device__ __forceinline__ void frag_to_tf32(Frag& f) {
    #pragma unroll
    for (int e = 0; e < f.num_elements; e++)
        f.x[e] = wmma::__float_to_tf32(f.x[e]);
}

// ---------------- tf32 pre-rounding pass ---------------------------------------
__global__ __launch_bounds__(256) void round_kernel(const float4* __restrict__ src,
                                                    int n4, int which)
{
    int i = blockIdx.x * blockDim.x + threadIdx.x;
    if (i >= n4) return;
    float4* dst = (which == 0) ? (float4*)g_x
                : (which == 1) ? (float4*)g_wq
                : (which == 2) ? (float4*)g_wk
                : (which == 3) ? (float4*)g_wv
                               : (float4*)g_wo;
    float4 v = src[i];
    v.x = wmma::__float_to_tf32(v.x);
    v.y = wmma::__float_to_tf32(v.y);
    v.z = wmma::__float_to_tf32(v.z);
    v.w = wmma::__float_to_tf32(v.w);
    dst[i] = v;
}

// =====================================================================
// WMMA tf32 GEMM, cp.async 3-stage pipeline, 2 CTAs/SM, BK=32.
// Block tile 128x128, 128 threads (4 warps 2x2), warp tile 64x64
// (4x4 m16n16 fragments) — 16 MMAs per 8 fragment loads per k8 step.
// Operands PRE-ROUNDED to tf32 — no cvt in the inner loop.
//  - TRANSB=true : B is [N,K] row-major (C = A * B^T)
//  - TRANSB=false: B is [K,N] row-major (C = A * B)
// ROUND_C: round accumulator to tf32 before store (chained GEMMs).
// =====================================================================
template <bool TRANSB, bool ROUND_C>
__device__ __forceinline__ void gemm_body(
    const float* __restrict__ A, const float* __restrict__ B, float* __restrict__ C,
    int lda, int ldb, int ldc, int m0, int n0, int kTiles, float* dynsm)
{
    float* smA = dynsm;                           // [NSTG][128*LDSA]
    float* smB = dynsm + NSTG * 128 * LDSA;       // [NSTG][128*LDSA] or [NSTG][32*LDSB]

    const int tid = threadIdx.x;
    const int wid = tid >> 5;
    const int warp_m = (wid >> 1) * 64;           // 0 or 64
    const int warp_n = (wid & 1) * 64;            // 0 or 64

    wmma::fragment<wmma::accumulator, 16, 16, 8, float> acc[4][4];
    #pragma unroll
    for (int mi = 0; mi < 4; mi++)
        #pragma unroll
        for (int ni = 0; ni < 4; ni++)
            wmma::fill_fragment(acc[mi][ni], 0.0f);

    auto issue = [&](int kt) {
        const int stg = kt % NSTG;
        const int k0 = kt * BK;
        float* dA = smA + stg * 128 * LDSA;
        #pragma unroll
        for (int r = 0; r < 8; r++) {
            int idx = tid + r * NTHR;      // 0..1023 float4s (128 rows x 8)
            int row = idx >> 3;            // 0..127
            int c4  = (idx & 7) << 2;      // 0..28
            cp16(dA + row * LDSA + c4, A + (size_t)(m0 + row) * lda + k0 + c4);
        }
        if (TRANSB) {
            float* dB = smB + stg * 128 * LDSA;
            #pragma unroll
            for (int r = 0; r < 8; r++) {
                int idx = tid + r * NTHR;
                int row = idx >> 3;
                int c4  = (idx & 7) << 2;
                cp16(dB + row * LDSA + c4, B + (size_t)(n0 + row) * ldb + k0 + c4);
            }
        } else {
            float* dB = smB + stg * 32 * LDSB;
            #pragma unroll
            for (int r = 0; r < 8; r++) {
                int idx = tid + r * NTHR;      // 0..1023 (32 krows x 32)
                int krow = idx >> 5;           // 0..31
                int c4   = (idx & 31) << 2;    // 0..124
                cp16(dB + krow * LDSB + c4, B + (size_t)(k0 + krow) * ldb + n0 + c4);
            }
        }
        CP_COMMIT();
    };

    issue(0);
    if (kTiles > 1) issue(1);
    for (int kt = 0; kt < kTiles; kt++) {
        CP_WAIT1();            // stage kt complete (kt+1 may be in flight)
        __syncthreads();       // also guards stage-buffer reuse
        if (kt + 2 < kTiles) issue(kt + 2);
        const int stg = kt % NSTG;
        const float* cA = smA + stg * 128 * LDSA;
        const float* cB = TRANSB ? (smB + stg * 128 * LDSA) : (smB + stg * 32 * LDSB);

        #pragma unroll
        for (int ks = 0; ks < BK; ks += 8) {
            wmma::fragment<wmma::matrix_a, 16, 16, 8, wmma::precision::tf32,
                           wmma::row_major> af[4];
            #pragma unroll
            for (int mi = 0; mi < 4; mi++)
                wmma::load_matrix_sync(af[mi], cA + (warp_m + mi * 16) * LDSA + ks, LDSA);
            if (TRANSB) {
                wmma::fragment<wmma::matrix_b, 16, 16, 8, wmma::precision::tf32,
                               wmma::col_major> bf[4];
                #pragma unroll
                for (int ni = 0; ni < 4; ni++)
                    wmma::load_matrix_sync(bf[ni], cB + (warp_n + ni * 16) * LDSA + ks, LDSA);
                #pragma unroll
                for (int mi = 0; mi < 4; mi++)
                    #pragma unroll
                    for (int ni = 0; ni < 4; ni++)
                        wmma::mma_sync(acc[mi][ni], af[mi], bf[ni], acc[mi][ni]);
            } else {
                wmma::fragment<wmma::matrix_b, 16, 16, 8, wmma::precision::tf32,
                               wmma::row_major> bf[4];
                #pragma unroll
                for (int ni = 0; ni < 4; ni++)
                    wmma::load_matrix_sync(bf[ni], cB + ks * LDSB + warp_n + ni * 16, LDSB);
                #pragma unroll
                for (int mi = 0; mi < 4; mi++)
                    #pragma unroll
                    for (int ni = 0; ni < 4; ni++)
                        wmma::mma_sync(acc[mi][ni], af[mi], bf[ni], acc[mi][ni]);
            }
        }
    }

    #pragma unroll
    for (int mi = 0; mi < 4; mi++)
        #pragma unroll
        for (int ni = 0; ni < 4; ni++) {
            if (ROUND_C) frag_to_tf32(acc[mi][ni]);
            size_t row = (size_t)(m0 + warp_m + mi * 16);
            int col = n0 + warp_n + ni * 16;
            wmma::store_matrix_sync(C + row * ldc + col, acc[mi][ni], ldc,
                                    wmma::mem_row_major);
        }
}

#define NT_SMEM ((2 * NSTG * 128 * LDSA) * (int)sizeof(float))                 // 110592 B
#define NN_SMEM ((NSTG * 128 * LDSA + NSTG * 32 * LDSB) * (int)sizeof(float))  // 105984 B

// ---------------- GEMM kernels -------------------------------------------------
__global__ __launch_bounds__(NTHR, 2) void qkv_gemm_kernel()
{
    extern __shared__ float dynsm[];
    const float* W = (blockIdx.z == 0) ? g_wq : (blockIdx.z == 1) ? g_wk : g_wv;
    float* C = g_qkv + (size_t)blockIdx.z * MN;
    gemm_body<true, false>(g_x, W, C, HID, HID, HID,
                           blockIdx.y * 128, blockIdx.x * 128, HID / BK, dynsm);
}

__global__ __launch_bounds__(NTHR, 2) void out_gemm_kernel(float* __restrict__ out)
{
    extern __shared__ float dynsm[];
    gemm_body<true, false>(g_attn_t, g_wo, out, HID, HID, HID,
                           blockIdx.y * 128, blockIdx.x * 128, HID / BK, dynsm);
}

// scores[z,q,k] = Q[z,q,:] . K[z,k,:] ; skip blocks fully above the diagonal
__global__ __launch_bounds__(NTHR, 2) void score_gemm_kernel()
{
    if (blockIdx.x > blockIdx.y) return;   // all k > all q in this block
    extern __shared__ float dynsm[];
    int z = blockIdx.z;
    const float* A = g_q + (size_t)z * SEQ * HD;
    const float* B = g_k + (size_t)z * SEQ * HD;
    float* C = g_scores + (size_t)z * SEQ * SEQ;
    gemm_body<true, false>(A, B, C, HD, HD, SEQ,
                           blockIdx.y * 128, blockIdx.x * 128, HD / BK, dynsm);
}

// O[z] = P[z] @ V[z] -> [B*S, H*D]; K-loop truncated at the causal diagonal.
// C rounded to tf32 (consumed as A by the out-projection).
__global__ __launch_bounds__(NTHR, 2) void pv_gemm_kernel()
{
    extern __shared__ float dynsm[];
    int z = blockIdx.z;
    int b = z / NH, h = z % NH;
    int m0 = blockIdx.y * 128;
    const float* A = g_scores + (size_t)z * SEQ * SEQ;   // [S,S] probs (pre-rounded)
    const float* B = g_v + (size_t)z * SEQ * HD;         // [S,HD]   (pre-rounded)
    float* C = g_attn_t + (size_t)b * SEQ * HID + (size_t)h * HD;
    int kT = (m0 + 128) / BK;          // only k <= q contribute
    gemm_body<false, true>(A, B, C, SEQ, HD, HID, m0, 0, kT, dynsm);
}

// ---------------- RoPE + transpose to [B,H,S,D]; writes tf32-rounded -----------
__global__ __launch_bounds__(256) void rope_transpose_kernel()
{
    long long idx = (long long)blockIdx.x * blockDim.x + threadIdx.x;
    const long long total = (long long)BSZ * NH * SEQ * 64;
    if (idx >= total) return;

    int d = (int)(idx % 64);  long long r = idx / 64;
    int s = (int)(r % SEQ);   r /= SEQ;
    int h = (int)(r % NH);
    int b = (int)(r / NH);

    double inv_freq = exp(-((double)(2 * d) / (double)HD) * log(10000.0));
    double ang = (double)s * inv_freq;
    double cd, sd;
    sincos(ang, &sd, &cd);
    float c  = (float)cd;
    float sn = (float)sd;

    size_t src = ((size_t)b * SEQ + s) * HID + (size_t)h * HD + d;   // [B*S, H*D]
    size_t dst = (((size_t)b * NH + h) * SEQ + s) * HD + d;          // [B,H,S,D]

    const float* Q0 = g_qkv;
    const float* K0 = g_qkv + MN;
    const float* V0 = g_qkv + 2 * MN;

    float q0 = Q0[src], q1 = Q0[src + 64];
    g_q[dst]      = wmma::__float_to_tf32(q0 * c - q1 * sn);
    g_q[dst + 64] = wmma::__float_to_tf32(q1 * c + q0 * sn);

    float k0 = K0[src], k1 = K0[src + 64];
    g_k[dst]      = wmma::__float_to_tf32(k0 * c - k1 * sn);
    g_k[dst + 64] = wmma::__float_to_tf32(k1 * c + k0 * sn);

    g_v[dst]      = wmma::__float_to_tf32(V0[src]);
    g_v[dst + 64] = wmma::__float_to_tf32(V0[src + 64]);
}

// ---------------- softmax; writes tf32-rounded probs ---------------------------
// Zero-fill only up to the 128-aligned block boundary PV actually reads.
__global__ __launch_bounds__(256) void softmax_kernel()
{
    const int warp = threadIdx.x >> 5;
    const int lane = threadIdx.x & 31;
    size_t row = (size_t)blockIdx.x * 8 + warp;            // 0 .. NZ*SEQ-1
    int q = (int)(row % SEQ);
    float* p = g_scores + row * (size_t)SEQ;
    const float scale = 0.08838834764831845f;              // 1/sqrt(128)

    float m = -INFINITY;
    for (int k = lane; k <= q; k += 32) m = fmaxf(m, p[k] * scale);
    #pragma unroll
    for (int o = 16; o; o >>= 1) m = fmaxf(m, __shfl_xor_sync(0xffffffffu, m, o));

    float ssum = 0.0f;
    for (int k = lane; k <= q; k += 32) ssum += __expf(p[k] * scale - m);
    #pragma unroll
    for (int o = 16; o; o >>= 1) ssum += __shfl_xor_sync(0xffffffffu, ssum, o);

    float inv = 1.0f / ssum;
    int kmax = ((q >> 7) + 1) << 7;    // PV reads k < kmax for this row's block
    for (int k = lane; k < kmax; k += 32)
        p[k] = (k <= q) ? wmma::__float_to_tf32(__expf(p[k] * scale - m) * inv) : 0.0f;
}

// ---------------- launch -------------------------------------------------------
extern "C" void kernel_launch(void* const* d_in, const int* in_sizes, int n_in,
                              void* d_out, int out_size)
{
    const float* X  = (const float*)d_in[0];
    const float* Wq = (const float*)d_in[1];
    const float* Wk = (const float*)d_in[2];
    const float* Wv = (const float*)d_in[3];
    const float* Wo = (const float*)d_in[4];
    float* out = (float*)d_out;

    cudaFuncSetAttribute(qkv_gemm_kernel,
                         cudaFuncAttributeMaxDynamicSharedMemorySize, NT_SMEM);
    cudaFuncSetAttribute(out_gemm_kernel,
                         cudaFuncAttributeMaxDynamicSharedMemorySize, NT_SMEM);
    cudaFuncSetAttribute(score_gemm_kernel,
                         cudaFuncAttributeMaxDynamicSharedMemorySize, NT_SMEM);
    cudaFuncSetAttribute(pv_gemm_kernel,
                         cudaFuncAttributeMaxDynamicSharedMemorySize, NN_SMEM);

    // 0. Pre-round X and weights to tf32
    round_kernel<<<(MN/4 + 255) / 256, 256>>>((const float4*)X,  MN/4,    0);
    round_kernel<<<(WELEM/4 + 255) / 256, 256>>>((const float4*)Wq, WELEM/4, 1);
    round_kernel<<<(WELEM/4 + 255) / 256, 256>>>((const float4*)Wk, WELEM/4, 2);
    round_kernel<<<(WELEM/4 + 255) / 256, 256>>>((const float4*)Wv, WELEM/4, 3);
    round_kernel<<<(WELEM/4 + 255) / 256, 256>>>((const float4*)Wo, WELEM/4, 4);

    // 1. QKV projections
    {
        dim3 grid(HID / 128, MROWS / 128, 3);
        qkv_gemm_kernel<<<grid, NTHR, NT_SMEM>>>();
    }
    // 2. RoPE + transpose
    {
        long long total = (long long)BSZ * NH * SEQ * 64;  // 4,194,304
        rope_transpose_kernel<<<(unsigned)((total + 255) / 256), 256>>>();
    }
    // 3. Scores = Q K^T (lower-triangle blocks only)
    {
        dim3 grid(SEQ / 128, SEQ / 128, NZ);
        score_gemm_kernel<<<grid, NTHR, NT_SMEM>>>();
    }
    // 4. Softmax
    {
        unsigned rows = NZ * SEQ;                 // 65536
        softmax_kernel<<<rows / 8, 256>>>();
    }
    // 5. O = P V
    {
        dim3 grid(1, SEQ / 128, NZ);
        pv_gemm_kernel<<<grid, NTHR, NN_SMEM>>>();
    }
    // 6. Output projection
    {
        dim3 grid(HID / 128, MROWS / 128);
        out_gemm_kernel<<<grid, NTHR, NT_SMEM>>>(out);
    }
}